// round 13
// baseline (speedup 1.0000x reference)
#include <cuda_runtime.h>
#include <cuda_bf16.h>
#include <math.h>

// Problem constants (fixed by reference: WINDOW=4, N=50000, E=400000, D=128)
#define WIN 4
#define NN  50000
#define EE  400000
#define DD  128

// -------- scratch (no allocations allowed; __device__ globals) --------
__device__ float g_tmp[NN * DD];     // GEMM output (pre-aggregation features)
__device__ float g_h[NN * DD];       // hidden activations between the two convs
__device__ int   g_cnt[NN];          // per-dst edge counts (histogram)
__device__ int   g_rowptr[NN + 1];   // CSR row pointers
__device__ int   g_cursor[NN];       // fill cursors (copy of rowptr)
__device__ int   g_src_perm[EE];     // src node per CSR slot
__device__ float g_w_perm[EE];       // edge weight per CSR slot

// ---------------------------------------------------------------------
// GEMM: C[N x 128] = A[N x 128] @ W[128 x 128]
// Tile: 64 rows x 128 cols, K chunked by 32, 256 threads, 8x4 micro-tile.
// ---------------------------------------------------------------------
__global__ __launch_bounds__(256) void gemm_kernel(
    const float* __restrict__ A, const float* __restrict__ Wm,
    float* __restrict__ C)
{
    __shared__ float At[32 * 65];   // [k][m], stride 65
    __shared__ float Bs[32 * 128];  // [k][c]

    const int block_row = blockIdx.x * 64;
    const int t  = threadIdx.x;
    const int tx = t & 31;
    const int ty = t >> 5;
    const int cols = tx * 4;

    float acc[8][4];
#pragma unroll
    for (int i = 0; i < 8; i++)
#pragma unroll
        for (int j = 0; j < 4; j++) acc[i][j] = 0.f;

    for (int k0 = 0; k0 < 128; k0 += 32) {
        // stage A chunk (64 rows x 32 k) transposed: 512 float4 slots
#pragma unroll
        for (int l = 0; l < 2; l++) {
            int idx = t + l * 256;
            int row = idx >> 3;
            int kq  = idx & 7;
            int grow = block_row + row;
            float4 v = make_float4(0.f, 0.f, 0.f, 0.f);
            if (grow < NN)
                v = *reinterpret_cast<const float4*>(A + (size_t)grow * DD + k0 + kq * 4);
            At[(kq * 4 + 0) * 65 + row] = v.x;
            At[(kq * 4 + 1) * 65 + row] = v.y;
            At[(kq * 4 + 2) * 65 + row] = v.z;
            At[(kq * 4 + 3) * 65 + row] = v.w;
        }
        // stage W chunk (32 k x 128 cols): 1024 float4 slots
#pragma unroll
        for (int l = 0; l < 4; l++) {
            int idx = t + l * 256;
            int row = idx >> 5;
            int cq  = idx & 31;
            float4 v = *reinterpret_cast<const float4*>(Wm + (size_t)(k0 + row) * DD + cq * 4);
            *reinterpret_cast<float4*>(&Bs[row * 128 + cq * 4]) = v;
        }
        __syncthreads();

#pragma unroll
        for (int k = 0; k < 32; k++) {
            float a[8];
#pragma unroll
            for (int i = 0; i < 8; i++) a[i] = At[k * 65 + ty * 8 + i];
            float4 b = *reinterpret_cast<const float4*>(&Bs[k * 128 + cols]);
#pragma unroll
            for (int i = 0; i < 8; i++) {
                acc[i][0] = fmaf(a[i], b.x, acc[i][0]);
                acc[i][1] = fmaf(a[i], b.y, acc[i][1]);
                acc[i][2] = fmaf(a[i], b.z, acc[i][2]);
                acc[i][3] = fmaf(a[i], b.w, acc[i][3]);
            }
        }
        __syncthreads();
    }

#pragma unroll
    for (int i = 0; i < 8; i++) {
        int row = block_row + ty * 8 + i;
        if (row < NN) {
            float4 v = make_float4(acc[i][0], acc[i][1], acc[i][2], acc[i][3]);
            *reinterpret_cast<float4*>(C + (size_t)row * DD + cols) = v;
        }
    }
}

// ---------------------------------------------------------------------
// CSR build: histogram -> single-block scan -> bucket fill
// ---------------------------------------------------------------------
__global__ __launch_bounds__(256) void zero_cnt_kernel(int* __restrict__ cnt)
{
    int i = blockIdx.x * blockDim.x + threadIdx.x;
    if (i < NN) cnt[i] = 0;
}

__global__ __launch_bounds__(256) void count_kernel(
    const int* __restrict__ ei, int* __restrict__ cnt)
{
    int e = blockIdx.x * blockDim.x + threadIdx.x;
    if (e >= EE) return;
    atomicAdd(cnt + __ldg(ei + EE + e), 1);
}

// Exclusive prefix scan over NN counts, single block of 1024 threads.
__global__ __launch_bounds__(1024) void scan_kernel(
    const int* __restrict__ cnt, int* __restrict__ rowptr,
    int* __restrict__ cursor)
{
    __shared__ int warp_sums[32];
    __shared__ int s_carry;
    const int t = threadIdx.x;
    const int lane = t & 31, wid = t >> 5;
    if (t == 0) s_carry = 0;
    __syncthreads();

    for (int base = 0; base < NN; base += 1024) {
        int i = base + t;
        int v = (i < NN) ? cnt[i] : 0;
        // inclusive warp scan
        int x = v;
#pragma unroll
        for (int o = 1; o < 32; o <<= 1) {
            int y = __shfl_up_sync(0xFFFFFFFFu, x, o);
            if (lane >= o) x += y;
        }
        if (lane == 31) warp_sums[wid] = x;
        __syncthreads();
        if (wid == 0) {
            int s = warp_sums[lane];
#pragma unroll
            for (int o = 1; o < 32; o <<= 1) {
                int y = __shfl_up_sync(0xFFFFFFFFu, s, o);
                if (lane >= o) s += y;
            }
            warp_sums[lane] = s;   // inclusive scan of warp sums
        }
        __syncthreads();
        int warp_off = (wid == 0) ? 0 : warp_sums[wid - 1];
        int excl = s_carry + warp_off + (x - v);
        if (i < NN) { rowptr[i] = excl; cursor[i] = excl; }
        __syncthreads();
        if (t == 0) s_carry += warp_sums[31];   // chunk total
        __syncthreads();
    }
    if (t == 0) rowptr[NN] = s_carry;
}

__global__ __launch_bounds__(256) void fill_kernel(
    const int* __restrict__ ei, const float* __restrict__ ew,
    int* __restrict__ cursor, int* __restrict__ src_perm,
    float* __restrict__ w_perm)
{
    int e = blockIdx.x * blockDim.x + threadIdx.x;
    if (e >= EE) return;
    int s = __ldg(ei + e);
    int d = __ldg(ei + EE + e);
    float w = __ldg(ew + e);
    int p = atomicAdd(cursor + d, 1);
    src_perm[p] = s;
    w_perm[p]  = w;
}

// ---------------------------------------------------------------------
// Aggregation: warp per destination node. Register accumulation, no
// atomics. Fused epilogue: out = ELU(sum + bias).
// ---------------------------------------------------------------------
__device__ __forceinline__ float elu1(float v) {
    return v > 0.f ? v : expm1f(v);
}

__global__ __launch_bounds__(256) void agg_kernel(
    const float* __restrict__ feat,       // [N x 128] (GEMM output)
    const int*   __restrict__ rowptr,
    const int*   __restrict__ src_perm,
    const float* __restrict__ w_perm,
    const float* __restrict__ b,          // [128]
    float* __restrict__ out)              // [N x 128]
{
    int warp = (blockIdx.x * blockDim.x + threadIdx.x) >> 5;
    int lane = threadIdx.x & 31;
    if (warp >= NN) return;

    int r0 = __ldg(rowptr + warp);
    int r1 = __ldg(rowptr + warp + 1);

    float4 acc = make_float4(0.f, 0.f, 0.f, 0.f);
    for (int j = r0; j < r1; j++) {
        int   s = __ldg(src_perm + j);
        float w = __ldg(w_perm + j);
        float4 v = *reinterpret_cast<const float4*>(feat + (size_t)s * DD + lane * 4);
        acc.x = fmaf(w, v.x, acc.x);
        acc.y = fmaf(w, v.y, acc.y);
        acc.z = fmaf(w, v.z, acc.z);
        acc.w = fmaf(w, v.w, acc.w);
    }

    float4 bb = __ldg(reinterpret_cast<const float4*>(b) + lane);
    float4 o;
    o.x = elu1(acc.x + bb.x);
    o.y = elu1(acc.y + bb.y);
    o.z = elu1(acc.z + bb.z);
    o.w = elu1(acc.w + bb.w);
    *reinterpret_cast<float4*>(out + (size_t)warp * DD + lane * 4) = o;
}

// ---------------------------------------------------------------------
// Bind inputs by ELEMENT COUNT (robust to metadata ordering).
// ---------------------------------------------------------------------
extern "C" void kernel_launch(void* const* d_in, const int* in_sizes, int n_in,
                              void* d_out, int out_size)
{
    const float* x  = nullptr;
    const int*   ei = nullptr;
    const float* ew = nullptr;
    const float* W0 = nullptr, *W1 = nullptr;
    const float* b0 = nullptr, *b1 = nullptr;

    for (int i = 0; i < n_in; i++) {
        long sz = in_sizes[i];
        if      (sz == (long)WIN * NN * DD)   x  = (const float*)d_in[i];
        else if (sz == (long)WIN * 2 * EE)    ei = (const int*)  d_in[i];
        else if (sz == (long)WIN * EE)        ew = (const float*)d_in[i];
        else if (sz == (long)WIN * DD * DD) { if (!W0) W0 = (const float*)d_in[i]; else W1 = (const float*)d_in[i]; }
        else if (sz == (long)WIN * DD)      { if (!b0) b0 = (const float*)d_in[i]; else b1 = (const float*)d_in[i]; }
    }

    float* out = (float*)d_out;   // [4, 50000, 128]

    float *tmp, *h, *wperm;
    int *cnt, *rowptr, *cursor, *sperm;
    cudaGetSymbolAddress((void**)&tmp,    g_tmp);
    cudaGetSymbolAddress((void**)&h,      g_h);
    cudaGetSymbolAddress((void**)&cnt,    g_cnt);
    cudaGetSymbolAddress((void**)&rowptr, g_rowptr);
    cudaGetSymbolAddress((void**)&cursor, g_cursor);
    cudaGetSymbolAddress((void**)&sperm,  g_src_perm);
    cudaGetSymbolAddress((void**)&wperm,  g_w_perm);

    const int gemm_blocks = (NN + 63) / 64;              // 782
    const int node_blocks = (NN + 255) / 256;            // 196
    const int edge_blocks = (EE + 255) / 256;            // 1563
    const int agg_blocks  = (NN * 32 + 255) / 256;       // 6250

    for (int w = 0; w < WIN; w++) {
        const float* xw  = x  + (size_t)w * NN * DD;
        const int*   eiw = ei + (size_t)w * 2 * EE;
        const float* eww = ew + (size_t)w * EE;
        const float* W0w = W0 + (size_t)w * DD * DD;
        const float* b0w = b0 + (size_t)w * DD;
        const float* W1w = W1 + (size_t)w * DD * DD;
        const float* b1w = b1 + (size_t)w * DD;
        float*       ow  = out + (size_t)w * NN * DD;

        // CSR build (shared by both convs of this window)
        zero_cnt_kernel<<<node_blocks, 256>>>(cnt);
        count_kernel<<<edge_blocks, 256>>>(eiw, cnt);
        scan_kernel<<<1, 1024>>>(cnt, rowptr, cursor);
        fill_kernel<<<edge_blocks, 256>>>(eiw, eww, cursor, sperm, wperm);

        // conv 1: h = ELU(agg(x @ W0) + b0)
        gemm_kernel<<<gemm_blocks, 256>>>(xw, W0w, tmp);
        agg_kernel<<<agg_blocks, 256>>>(tmp, rowptr, sperm, wperm, b0w, h);

        // conv 2: out = ELU(agg(h @ W1) + b1)
        gemm_kernel<<<gemm_blocks, 256>>>(h, W1w, tmp);
        agg_kernel<<<agg_blocks, 256>>>(tmp, rowptr, sperm, wperm, b1w, ow);
    }
}

// round 14
// speedup vs baseline: 1.0058x; 1.0058x over previous
#include <cuda_runtime.h>
#include <cuda_bf16.h>
#include <math.h>

// Problem constants (fixed by reference: WINDOW=4, N=50000, E=400000, D=128)
#define WIN 4
#define NN  50000
#define EE  400000
#define DD  128

// -------- scratch (no allocations allowed; __device__ globals) --------
__device__ float g_tmp[NN * DD];     // GEMM output (pre-aggregation features)
__device__ float g_h[NN * DD];       // hidden activations between the two convs
__device__ int   g_cnt[NN];          // per-dst edge counts (histogram)
__device__ int   g_rowptr[NN + 1];   // CSR row pointers
__device__ int   g_cursor[NN];       // fill cursors (copy of rowptr)
__device__ int   g_src_perm[EE];     // src node per CSR slot
__device__ float g_w_perm[EE];       // edge weight per CSR slot

// ---------------------------------------------------------------------
// GEMM: C[N x 128] = A[N x 128] @ W[128 x 128]
// Tile: 64 rows x 128 cols, K chunked by 32, 256 threads, 8x4 micro-tile.
// ---------------------------------------------------------------------
__global__ __launch_bounds__(256) void gemm_kernel(
    const float* __restrict__ A, const float* __restrict__ Wm,
    float* __restrict__ C)
{
    __shared__ float At[32 * 65];   // [k][m], stride 65
    __shared__ float Bs[32 * 128];  // [k][c]

    const int block_row = blockIdx.x * 64;
    const int t  = threadIdx.x;
    const int tx = t & 31;
    const int ty = t >> 5;
    const int cols = tx * 4;

    float acc[8][4];
#pragma unroll
    for (int i = 0; i < 8; i++)
#pragma unroll
        for (int j = 0; j < 4; j++) acc[i][j] = 0.f;

    for (int k0 = 0; k0 < 128; k0 += 32) {
        // stage A chunk (64 rows x 32 k) transposed: 512 float4 slots
#pragma unroll
        for (int l = 0; l < 2; l++) {
            int idx = t + l * 256;
            int row = idx >> 3;
            int kq  = idx & 7;
            int grow = block_row + row;
            float4 v = make_float4(0.f, 0.f, 0.f, 0.f);
            if (grow < NN)
                v = *reinterpret_cast<const float4*>(A + (size_t)grow * DD + k0 + kq * 4);
            At[(kq * 4 + 0) * 65 + row] = v.x;
            At[(kq * 4 + 1) * 65 + row] = v.y;
            At[(kq * 4 + 2) * 65 + row] = v.z;
            At[(kq * 4 + 3) * 65 + row] = v.w;
        }
        // stage W chunk (32 k x 128 cols): 1024 float4 slots
#pragma unroll
        for (int l = 0; l < 4; l++) {
            int idx = t + l * 256;
            int row = idx >> 5;
            int cq  = idx & 31;
            float4 v = *reinterpret_cast<const float4*>(Wm + (size_t)(k0 + row) * DD + cq * 4);
            *reinterpret_cast<float4*>(&Bs[row * 128 + cq * 4]) = v;
        }
        __syncthreads();

#pragma unroll
        for (int k = 0; k < 32; k++) {
            float a[8];
#pragma unroll
            for (int i = 0; i < 8; i++) a[i] = At[k * 65 + ty * 8 + i];
            float4 b = *reinterpret_cast<const float4*>(&Bs[k * 128 + cols]);
#pragma unroll
            for (int i = 0; i < 8; i++) {
                acc[i][0] = fmaf(a[i], b.x, acc[i][0]);
                acc[i][1] = fmaf(a[i], b.y, acc[i][1]);
                acc[i][2] = fmaf(a[i], b.z, acc[i][2]);
                acc[i][3] = fmaf(a[i], b.w, acc[i][3]);
            }
        }
        __syncthreads();
    }

#pragma unroll
    for (int i = 0; i < 8; i++) {
        int row = block_row + ty * 8 + i;
        if (row < NN) {
            float4 v = make_float4(acc[i][0], acc[i][1], acc[i][2], acc[i][3]);
            *reinterpret_cast<float4*>(C + (size_t)row * DD + cols) = v;
        }
    }
}

// ---------------------------------------------------------------------
// CSR build: histogram -> single-block scan -> bucket fill
// ---------------------------------------------------------------------
__global__ __launch_bounds__(256) void zero_cnt_kernel(int* __restrict__ cnt)
{
    int i = blockIdx.x * blockDim.x + threadIdx.x;
    if (i < NN) cnt[i] = 0;
}

__global__ __launch_bounds__(256) void count_kernel(
    const int* __restrict__ ei, int* __restrict__ cnt)
{
    int e = blockIdx.x * blockDim.x + threadIdx.x;
    if (e >= EE) return;
    atomicAdd(cnt + __ldg(ei + EE + e), 1);
}

// Exclusive prefix scan over NN counts, single block of 1024 threads.
__global__ __launch_bounds__(1024) void scan_kernel(
    const int* __restrict__ cnt, int* __restrict__ rowptr,
    int* __restrict__ cursor)
{
    __shared__ int warp_sums[32];
    __shared__ int s_carry;
    const int t = threadIdx.x;
    const int lane = t & 31, wid = t >> 5;
    if (t == 0) s_carry = 0;
    __syncthreads();

    for (int base = 0; base < NN; base += 1024) {
        int i = base + t;
        int v = (i < NN) ? cnt[i] : 0;
        // inclusive warp scan
        int x = v;
#pragma unroll
        for (int o = 1; o < 32; o <<= 1) {
            int y = __shfl_up_sync(0xFFFFFFFFu, x, o);
            if (lane >= o) x += y;
        }
        if (lane == 31) warp_sums[wid] = x;
        __syncthreads();
        if (wid == 0) {
            int s = warp_sums[lane];
#pragma unroll
            for (int o = 1; o < 32; o <<= 1) {
                int y = __shfl_up_sync(0xFFFFFFFFu, s, o);
                if (lane >= o) s += y;
            }
            warp_sums[lane] = s;   // inclusive scan of warp sums
        }
        __syncthreads();
        int warp_off = (wid == 0) ? 0 : warp_sums[wid - 1];
        int excl = s_carry + warp_off + (x - v);
        if (i < NN) { rowptr[i] = excl; cursor[i] = excl; }
        __syncthreads();
        if (t == 0) s_carry += warp_sums[31];   // chunk total
        __syncthreads();
    }
    if (t == 0) rowptr[NN] = s_carry;
}

__global__ __launch_bounds__(256) void fill_kernel(
    const int* __restrict__ ei, const float* __restrict__ ew,
    int* __restrict__ cursor, int* __restrict__ src_perm,
    float* __restrict__ w_perm)
{
    int e = blockIdx.x * blockDim.x + threadIdx.x;
    if (e >= EE) return;
    int s = __ldg(ei + e);
    int d = __ldg(ei + EE + e);
    float w = __ldg(ew + e);
    int p = atomicAdd(cursor + d, 1);
    src_perm[p] = s;
    w_perm[p]  = w;
}

// ---------------------------------------------------------------------
// Aggregation: warp per destination node. Register accumulation, no
// atomics. Fused epilogue: out = ELU(sum + bias).
// ---------------------------------------------------------------------
__device__ __forceinline__ float elu1(float v) {
    return v > 0.f ? v : expm1f(v);
}

__global__ __launch_bounds__(256) void agg_kernel(
    const float* __restrict__ feat,       // [N x 128] (GEMM output)
    const int*   __restrict__ rowptr,
    const int*   __restrict__ src_perm,
    const float* __restrict__ w_perm,
    const float* __restrict__ b,          // [128]
    float* __restrict__ out)              // [N x 128]
{
    int warp = (blockIdx.x * blockDim.x + threadIdx.x) >> 5;
    int lane = threadIdx.x & 31;
    if (warp >= NN) return;

    int r0 = __ldg(rowptr + warp);
    int r1 = __ldg(rowptr + warp + 1);

    float4 acc = make_float4(0.f, 0.f, 0.f, 0.f);
    for (int j = r0; j < r1; j++) {
        int   s = __ldg(src_perm + j);
        float w = __ldg(w_perm + j);
        float4 v = *reinterpret_cast<const float4*>(feat + (size_t)s * DD + lane * 4);
        acc.x = fmaf(w, v.x, acc.x);
        acc.y = fmaf(w, v.y, acc.y);
        acc.z = fmaf(w, v.z, acc.z);
        acc.w = fmaf(w, v.w, acc.w);
    }

    float4 bb = __ldg(reinterpret_cast<const float4*>(b) + lane);
    float4 o;
    o.x = elu1(acc.x + bb.x);
    o.y = elu1(acc.y + bb.y);
    o.z = elu1(acc.z + bb.z);
    o.w = elu1(acc.w + bb.w);
    *reinterpret_cast<float4*>(out + (size_t)warp * DD + lane * 4) = o;
}

// ---------------------------------------------------------------------
// Bind inputs by ELEMENT COUNT (robust to metadata ordering).
// ---------------------------------------------------------------------
extern "C" void kernel_launch(void* const* d_in, const int* in_sizes, int n_in,
                              void* d_out, int out_size)
{
    const float* x  = nullptr;
    const int*   ei = nullptr;
    const float* ew = nullptr;
    const float* W0 = nullptr, *W1 = nullptr;
    const float* b0 = nullptr, *b1 = nullptr;

    for (int i = 0; i < n_in; i++) {
        long sz = in_sizes[i];
        if      (sz == (long)WIN * NN * DD)   x  = (const float*)d_in[i];
        else if (sz == (long)WIN * 2 * EE)    ei = (const int*)  d_in[i];
        else if (sz == (long)WIN * EE)        ew = (const float*)d_in[i];
        else if (sz == (long)WIN * DD * DD) { if (!W0) W0 = (const float*)d_in[i]; else W1 = (const float*)d_in[i]; }
        else if (sz == (long)WIN * DD)      { if (!b0) b0 = (const float*)d_in[i]; else b1 = (const float*)d_in[i]; }
    }

    float* out = (float*)d_out;   // [4, 50000, 128]

    float *tmp, *h, *wperm;
    int *cnt, *rowptr, *cursor, *sperm;
    cudaGetSymbolAddress((void**)&tmp,    g_tmp);
    cudaGetSymbolAddress((void**)&h,      g_h);
    cudaGetSymbolAddress((void**)&cnt,    g_cnt);
    cudaGetSymbolAddress((void**)&rowptr, g_rowptr);
    cudaGetSymbolAddress((void**)&cursor, g_cursor);
    cudaGetSymbolAddress((void**)&sperm,  g_src_perm);
    cudaGetSymbolAddress((void**)&wperm,  g_w_perm);

    const int gemm_blocks = (NN + 63) / 64;              // 782
    const int node_blocks = (NN + 255) / 256;            // 196
    const int edge_blocks = (EE + 255) / 256;            // 1563
    const int agg_blocks  = (NN * 32 + 255) / 256;       // 6250

    for (int w = 0; w < WIN; w++) {
        const float* xw  = x  + (size_t)w * NN * DD;
        const int*   eiw = ei + (size_t)w * 2 * EE;
        const float* eww = ew + (size_t)w * EE;
        const float* W0w = W0 + (size_t)w * DD * DD;
        const float* b0w = b0 + (size_t)w * DD;
        const float* W1w = W1 + (size_t)w * DD * DD;
        const float* b1w = b1 + (size_t)w * DD;
        float*       ow  = out + (size_t)w * NN * DD;

        // CSR build (shared by both convs of this window)
        zero_cnt_kernel<<<node_blocks, 256>>>(cnt);
        count_kernel<<<edge_blocks, 256>>>(eiw, cnt);
        scan_kernel<<<1, 1024>>>(cnt, rowptr, cursor);
        fill_kernel<<<edge_blocks, 256>>>(eiw, eww, cursor, sperm, wperm);

        // conv 1: h = ELU(agg(x @ W0) + b0)
        gemm_kernel<<<gemm_blocks, 256>>>(xw, W0w, tmp);
        agg_kernel<<<agg_blocks, 256>>>(tmp, rowptr, sperm, wperm, b0w, h);

        // conv 2: out = ELU(agg(h @ W1) + b1)
        gemm_kernel<<<gemm_blocks, 256>>>(h, W1w, tmp);
        agg_kernel<<<agg_blocks, 256>>>(tmp, rowptr, sperm, wperm, b1w, ow);
    }
}